// round 3
// baseline (speedup 1.0000x reference)
#include <cuda_runtime.h>
#include <cuda_bf16.h>
#include <math.h>

// ---------------- problem constants ----------------
#define BB 16
#define LL 512
#define HH 256
#define NHH 8
#define HDD 32
#define ITER 2
#define PCOLS 272        // NH * 34  (slots: 0=a1, 1=a2, 2..33=Fw cols)
#define NROWS (BB*LL)    // 8192
#define YROWS (BB*(LL+1))// 8208
#define NEGV  (-9e15f)

// ---------------- scratch (device globals, no alloc) ----------------
__device__ float g_W1[HH*PCOLS];
__device__ float g_W2[HH*PCOLS];
__device__ float g_W3[HH*PCOLS];
__device__ float g_cb[PCOLS];
__device__ float g_D [NROWS*PCOLS];
__device__ float g_P [NROWS*PCOLS];
__device__ float g_R [BB*PCOLS];
__device__ float g_nodes[NROWS*HH];
__device__ float g_xn   [NROWS*HH];
__device__ float g_temp [NROWS*HH];
__device__ float g_kmat [YROWS*HH];
__device__ float g_relay[BB*HH];
__device__ float g_q    [BB*HH];
__device__ float g_attv [BB*HH];
__device__ float g_skT  [2*HH*HH];

// ---------------- weight folding ----------------
// W1[k][c] = sum_d Wq[n][d][k] * cvec_c[d],  cvec: slot0=a1[:H], slot1=a2[:H], slot s=Fw[:H, s-2]
__global__ __launch_bounds__(256) void build_w1(const float* __restrict__ Wq,
        const float* __restrict__ a1, const float* __restrict__ a2,
        const float* __restrict__ fw, float* __restrict__ W1)
{
    int c = blockIdx.x;                 // 0..271
    int n = c / 34, s = c % 34;
    int t = threadIdx.x;                // 0..255
    __shared__ float cvec[256];
    float cv;
    if (s == 0)      cv = a1[n*768 + t];
    else if (s == 1) cv = a2[n*768 + t];
    else             cv = fw[(size_t)n*24576 + t*32 + (s-2)];
    cvec[t] = cv;
    __syncthreads();
    const float* wqn = Wq + (size_t)n*65536;
    float sum = 0.f;
    #pragma unroll 8
    for (int d = 0; d < 256; d++) sum += wqn[d*256 + t] * cvec[d];
    W1[t*PCOLS + c] = sum;
}

// W2 (even=data part of ax), W3 (odd=relay part), cb = bq.cvec, skT transposes
__global__ __launch_bounds__(256) void build_misc(const float* __restrict__ a1,
        const float* __restrict__ a2, const float* __restrict__ fw,
        const float* __restrict__ bq, const float* __restrict__ skw,
        float* __restrict__ W2, float* __restrict__ W3,
        float* __restrict__ cb, float* __restrict__ skT)
{
    int idx = blockIdx.x*256 + threadIdx.x;
    if (idx < HH*PCOLS) {
        int k = idx / PCOLS, c = idx % PCOLS;
        int n = c / 34, s = c % 34;
        int re = 256 + 2*k, ro = re + 1;
        float ve, vo;
        if (s == 0)      { ve = a1[n*768+re]; vo = a1[n*768+ro]; }
        else if (s == 1) { ve = a2[n*768+re]; vo = a2[n*768+ro]; }
        else { ve = fw[(size_t)n*24576 + re*32 + (s-2)];
               vo = fw[(size_t)n*24576 + ro*32 + (s-2)]; }
        W2[idx] = ve; W3[idx] = vo;
    }
    int idx2 = idx - HH*PCOLS;
    if (idx2 >= 0 && idx2 < 2*65536) {
        int i = idx2 >> 16, rem = idx2 & 65535;
        int k = rem >> 8, c = rem & 255;
        skT[(size_t)i*65536 + k*256 + c] = skw[(size_t)i*65536 + c*256 + k];
    }
    if (idx < PCOLS) {
        int n = idx / 34, s = idx % 34;
        float sum = 0.f;
        for (int d = 0; d < 256; d++) {
            float cv = (s==0) ? a1[n*768+d] : (s==1) ? a2[n*768+d]
                     : fw[(size_t)n*24576 + d*32 + (s-2)];
            sum += bq[n*256+d] * cv;
        }
        cb[idx] = sum;
    }
}

__global__ __launch_bounds__(256) void relay_init(const float* __restrict__ data,
                                                  float* __restrict__ relay)
{
    int b = blockIdx.x, h = threadIdx.x;
    float s = 0.f;
    for (int l = 0; l < LL; l++) s += data[((size_t)b*LL + l)*HH + h];
    relay[b*HH + h] = s * (1.f/512.f);
}

// ---------------- GEMM: C[M,N] = A[M,256] @ B[256,N] (+ epilogue) ----------------
#define EP_BIAS 1
#define EP_FC   2
#define AMODE_Y 4
__global__ __launch_bounds__(256) void gemm_kernel(const float* __restrict__ A,
        const float* __restrict__ Bm, const float* __restrict__ bias,
        float* __restrict__ C, int M, int N, int mode,
        const float* __restrict__ relayv, const float* __restrict__ resid)
{
    __shared__ __align__(16) float As[16][64];
    __shared__ __align__(16) float Bs[16][64];
    int tid = threadIdx.x;
    int row0 = blockIdx.x * 64;
    int col0 = blockIdx.y * 64;
    int tx = tid & 15, ty = tid >> 4;
    int aRow = tid >> 2;          // 0..63
    int aCol = (tid & 3) * 4;     // 0,4,8,12
    int bRow = tid >> 4;          // 0..15
    int bCol = (tid & 15) * 4;
    float acc[4][4];
    #pragma unroll
    for (int i = 0; i < 4; i++)
        #pragma unroll
        for (int j = 0; j < 4; j++) acc[i][j] = 0.f;

    for (int k0 = 0; k0 < 256; k0 += 16) {
        int gr = row0 + aRow;
        float4 av = make_float4(0.f,0.f,0.f,0.f);
        if (gr < M) {
            const float* arow;
            if (mode & AMODE_Y) {
                int b = gr / 513, lr = gr - b*513;
                arow = (lr == 0) ? (relayv + b*HH)
                                 : (A + (size_t)(b*LL + lr - 1)*HH);
            } else arow = A + (size_t)gr*256;
            av = *(const float4*)(arow + k0 + aCol);
        }
        As[aCol+0][aRow] = av.x; As[aCol+1][aRow] = av.y;
        As[aCol+2][aRow] = av.z; As[aCol+3][aRow] = av.w;
        int gk = k0 + bRow;
        #pragma unroll
        for (int q = 0; q < 4; q++) {
            int gc = col0 + bCol + q;
            Bs[bRow][bCol+q] = (gc < N) ? Bm[(size_t)gk*N + gc] : 0.f;
        }
        __syncthreads();
        #pragma unroll
        for (int kk = 0; kk < 16; kk++) {
            float4 a4 = *(const float4*)&As[kk][ty*4];
            float4 b4 = *(const float4*)&Bs[kk][tx*4];
            float ar[4] = {a4.x,a4.y,a4.z,a4.w};
            float br[4] = {b4.x,b4.y,b4.z,b4.w};
            #pragma unroll
            for (int i = 0; i < 4; i++)
                #pragma unroll
                for (int j = 0; j < 4; j++) acc[i][j] += ar[i]*br[j];
        }
        __syncthreads();
    }
    #pragma unroll
    for (int i = 0; i < 4; i++) {
        int r = row0 + ty*4 + i;
        if (r >= M) continue;
        #pragma unroll
        for (int j = 0; j < 4; j++) {
            int c = col0 + tx*4 + j;
            if (c >= N) continue;
            float v = acc[i][j];
            if (mode & EP_BIAS) v += bias[c];
            if (mode & EP_FC) {
                v = v > 0.f ? v : 0.01f*v;
                v += resid[(size_t)r*N + c];
            }
            C[(size_t)r*N + c] = v;
        }
    }
}

// ---------------- LayerNorm ----------------
__global__ __launch_bounds__(256) void ln_kernel(const float* __restrict__ nodes,
        const float* __restrict__ gam, const float* __restrict__ bet,
        float* __restrict__ xn)
{
    int r = blockIdx.x, t = threadIdx.x;
    float x = nodes[(size_t)r*HH + t];
    float s = x, s2 = x*x;
    #pragma unroll
    for (int off = 16; off; off >>= 1) {
        s  += __shfl_xor_sync(0xffffffffu, s,  off);
        s2 += __shfl_xor_sync(0xffffffffu, s2, off);
    }
    __shared__ float sh1[8], sh2[8];
    int w = t >> 5, lane = t & 31;
    if (lane == 0) { sh1[w] = s; sh2[w] = s2; }
    __syncthreads();
    s = 0.f; s2 = 0.f;
    #pragma unroll
    for (int i = 0; i < 8; i++) { s += sh1[i]; s2 += sh2[i]; }
    float m = s * (1.f/256.f);
    float v = s2 * (1.f/256.f) - m*m;
    xn[(size_t)r*HH + t] = (x - m) * rsqrtf(v + 1e-5f) * gam[t] + bet[t];
}

// ---------------- relay projection: R = relay @ W3 ----------------
__global__ void relayproj(const float* __restrict__ relay,
        const float* __restrict__ W3, float* __restrict__ R)
{
    int b = blockIdx.x, c = threadIdx.x; // 272 threads
    __shared__ float vsh[256];
    if (c < 256) vsh[c] = relay[b*HH + c];
    __syncthreads();
    float s = 0.f;
    #pragma unroll 8
    for (int k = 0; k < 256; k++) s += vsh[k] * W3[k*PCOLS + c];
    R[b*PCOLS + c] = s;
}

// ---------------- GAT attention (fused softmax + AV) ----------------
// one block per (head n, batch b): g tile in shared; warp per row.
__global__ __launch_bounds__(256) void gat_att(const float* __restrict__ P,
        const float* __restrict__ D, const float* __restrict__ R,
        const float* __restrict__ Fb, const int* __restrict__ edge,
        float* __restrict__ temp)
{
    extern __shared__ float sm[];
    float* gsh  = sm;                 // [512][33]
    float* eish = sm + 512*33;        // [512]
    float* ejsh = eish + 512;         // [512]
    int blk = blockIdx.x;
    int n = blk >> 4, b = blk & 15;
    int tid = threadIdx.x;
    int base = n * 34;
    float Rr0 = R[b*PCOLS + base];
    float Rr1 = R[b*PCOLS + base + 1];

    int d  = tid & 31;
    int j0 = tid >> 5;
    float Rg = R[b*PCOLS + base + 2 + d];
    for (int j = j0; j < 512; j += 8) {
        size_t idx = (size_t)(b*LL + j)*PCOLS + base + 2 + d;
        gsh[j*33 + d] = P[idx] + D[idx] + Rg;
    }
    for (int j = tid; j < 512; j += 256) {
        size_t idx = (size_t)(b*LL + j)*PCOLS + base;
        eish[j] = P[idx]   + D[idx]   + Rr0;
        ejsh[j] = P[idx+1] + D[idx+1] + Rr1;
    }
    __syncthreads();

    int warp = tid >> 5, lane = tid & 31;
    float Fbv = Fb[n*32 + lane];
    const int* erow_base = edge + (size_t)b*LL*LL;

    for (int i = warp; i < 512; i += 8) {
        float ei = eish[i];
        const int* erow = erow_base + (size_t)i*LL;
        float e16[16];
        float m = -INFINITY;
        #pragma unroll
        for (int t = 0; t < 16; t++) {
            int j = t*32 + lane;
            float e = ei + ejsh[j];
            e = e >= 0.f ? e : 0.2f*e;
            if (erow[j] <= 0) e = NEGV;
            e16[t] = e;
            m = fmaxf(m, e);
        }
        #pragma unroll
        for (int off = 16; off; off >>= 1)
            m = fmaxf(m, __shfl_xor_sync(0xffffffffu, m, off));
        float s = 0.f;
        float acc[32];
        #pragma unroll
        for (int d2 = 0; d2 < 32; d2++) acc[d2] = 0.f;
        #pragma unroll
        for (int t = 0; t < 16; t++) {
            int j = t*32 + lane;
            float w = __expf(e16[t] - m);
            s += w;
            const float* gj = &gsh[j*33];
            #pragma unroll
            for (int d2 = 0; d2 < 32; d2++) acc[d2] += w * gj[d2];
        }
        #pragma unroll
        for (int off = 16; off; off >>= 1) {
            s += __shfl_xor_sync(0xffffffffu, s, off);
            #pragma unroll
            for (int d2 = 0; d2 < 32; d2++)
                acc[d2] += __shfl_xor_sync(0xffffffffu, acc[d2], off);
        }
        float outv = 0.f;
        #pragma unroll
        for (int d2 = 0; d2 < 32; d2++) if (lane == d2) outv = acc[d2];
        outv = outv / s + Fbv;
        outv = outv > 0.f ? outv : expm1f(outv);   // elu
        temp[(size_t)(b*LL + i)*HH + n*32 + lane] = outv;
    }
}

// ---------------- small vec @ W.T (+bias, optional leaky) ----------------
__global__ __launch_bounds__(256) void vecmm(const float* __restrict__ vin,
        const float* __restrict__ W, const float* __restrict__ bias,
        float* __restrict__ vout, int lrelu)
{
    int b = blockIdx.x, c = threadIdx.x;
    __shared__ float vsh[256];
    vsh[c] = vin[b*HH + c];
    __syncthreads();
    const float* wr = W + (size_t)c*256;
    float s = bias[c];
    #pragma unroll 8
    for (int k = 0; k < 256; k++) s += wr[k] * vsh[k];
    if (lrelu) s = s > 0.f ? s : 0.01f*s;
    vout[b*HH + c] = s;
}

// ---------------- star attention ----------------
__global__ __launch_bounds__(256) void star_att(const float* __restrict__ q,
        const float* __restrict__ kmat, const int* __restrict__ mask,
        float* __restrict__ att)
{
    int b = blockIdx.x;
    int warp = threadIdx.x >> 5, lane = threadIdx.x & 31;
    __shared__ float qsh[8][32];
    qsh[warp][lane] = q[b*HH + warp*32 + lane];
    __syncwarp();
    const float scale = 0.17677669529663687f;   // 1/sqrt(32)
    float pre[17];
    float m = -INFINITY;
    #pragma unroll
    for (int t = 0; t < 17; t++) {
        int l = t*32 + lane;
        float p = -INFINITY;
        if (l < 513) {
            bool masked = (l > 0) && (mask[b*LL + l - 1] == 0);
            if (!masked) {
                const float* kr = kmat + ((size_t)b*513 + l)*HH + warp*32;
                float sacc = 0.f;
                #pragma unroll
                for (int d2 = 0; d2 < 32; d2++) sacc += qsh[warp][d2]*kr[d2];
                p = sacc * scale;
            }
        }
        pre[t] = p;
        m = fmaxf(m, p);
    }
    #pragma unroll
    for (int off = 16; off; off >>= 1)
        m = fmaxf(m, __shfl_xor_sync(0xffffffffu, m, off));
    float s = 0.f;
    float acc[32];
    #pragma unroll
    for (int d2 = 0; d2 < 32; d2++) acc[d2] = 0.f;
    #pragma unroll
    for (int t = 0; t < 17; t++) {
        int l = t*32 + lane;
        if (l < 513) {
            float w = __expf(pre[t] - m);   // 0 for masked
            s += w;
            const float* kr = kmat + ((size_t)b*513 + l)*HH + warp*32;
            #pragma unroll
            for (int d2 = 0; d2 < 32; d2++) acc[d2] += w * kr[d2];
        }
    }
    #pragma unroll
    for (int off = 16; off; off >>= 1) {
        s += __shfl_xor_sync(0xffffffffu, s, off);
        #pragma unroll
        for (int d2 = 0; d2 < 32; d2++)
            acc[d2] += __shfl_xor_sync(0xffffffffu, acc[d2], off);
    }
    float outv = 0.f;
    #pragma unroll
    for (int d2 = 0; d2 < 32; d2++) if (lane == d2) outv = acc[d2];
    att[b*HH + warp*32 + lane] = outv / s;
}

// ---------------- mask padded nodes ----------------
__global__ __launch_bounds__(256) void mask_nodes(const int* __restrict__ mask,
                                                  float* __restrict__ nodes)
{
    int idx = blockIdx.x*256 + threadIdx.x;
    int r = idx >> 8;
    int b = r >> 9, l = r & 511;
    if (mask[b*LL + l] == 0) nodes[idx] = 0.f;
}

// ---------------- launch ----------------
extern "C" void kernel_launch(void* const* d_in, const int* in_sizes, int n_in,
                              void* d_out, int out_size)
{
    const float* data   = (const float*)d_in[0];
    const float* WQw    = (const float*)d_in[1];
    const float* WQb    = (const float*)d_in[2];
    const float* a1     = (const float*)d_in[3];
    const float* a2     = (const float*)d_in[4];
    const float* fcw_g  = (const float*)d_in[5];   // gat_fc_w
    const float* fcb_g  = (const float*)d_in[6];   // gat_fc_b
    const float* norm_g = (const float*)d_in[7];
    const float* norm_b = (const float*)d_in[8];
    const float* sq_w   = (const float*)d_in[9];
    const float* sq_b   = (const float*)d_in[10];
    const float* sk_w   = (const float*)d_in[11];
    const float* sk_b   = (const float*)d_in[12];
    const float* so_w   = (const float*)d_in[13];
    const float* so_b   = (const float*)d_in[14];
    const float* fc_w   = (const float*)d_in[15];
    const float* fc_b   = (const float*)d_in[16];
    const int*   mask   = (const int*)d_in[17];
    const int*   edge   = (const int*)d_in[18];

    float *W1,*W2,*W3,*cb,*D,*P,*R,*nodes,*xn,*temp,*kmat,*relay,*qb,*attb,*skT;
    cudaGetSymbolAddress((void**)&W1, g_W1);
    cudaGetSymbolAddress((void**)&W2, g_W2);
    cudaGetSymbolAddress((void**)&W3, g_W3);
    cudaGetSymbolAddress((void**)&cb, g_cb);
    cudaGetSymbolAddress((void**)&D,  g_D);
    cudaGetSymbolAddress((void**)&P,  g_P);
    cudaGetSymbolAddress((void**)&R,  g_R);
    cudaGetSymbolAddress((void**)&nodes, g_nodes);
    cudaGetSymbolAddress((void**)&xn,    g_xn);
    cudaGetSymbolAddress((void**)&temp,  g_temp);
    cudaGetSymbolAddress((void**)&kmat,  g_kmat);
    cudaGetSymbolAddress((void**)&relay, g_relay);
    cudaGetSymbolAddress((void**)&qb,    g_q);
    cudaGetSymbolAddress((void**)&attb,  g_attv);
    cudaGetSymbolAddress((void**)&skT,   g_skT);

    cudaFuncSetAttribute(gat_att, cudaFuncAttributeMaxDynamicSharedMemorySize, 72*1024);

    build_w1<<<PCOLS, 256>>>(WQw, a1, a2, fcw_g, W1);
    build_misc<<<784, 256>>>(a1, a2, fcw_g, WQb, sk_w, W2, W3, cb, skT);
    relay_init<<<BB, 256>>>(data, relay);
    cudaMemcpyAsync(nodes, data, (size_t)NROWS*HH*sizeof(float),
                    cudaMemcpyDeviceToDevice);
    gemm_kernel<<<dim3(128,5), 256>>>(data, W2, nullptr, D, NROWS, PCOLS, 0,
                                      nullptr, nullptr);

    for (int i = 0; i < ITER; i++) {
        ln_kernel<<<NROWS, 256>>>(nodes, norm_g + i*HH, norm_b + i*HH, xn);
        gemm_kernel<<<dim3(128,5), 256>>>(xn, W1, cb, P, NROWS, PCOLS, EP_BIAS,
                                          nullptr, nullptr);
        relayproj<<<BB, PCOLS>>>(relay, W3, R);
        gat_att<<<128, 256, 72*1024>>>(P, D, R, fcb_g, edge, temp);
        gemm_kernel<<<dim3(128,4), 256>>>(temp, fc_w, fc_b, nodes, NROWS, HH,
                                          EP_BIAS|EP_FC, nullptr, nodes);
        vecmm<<<BB, 256>>>(relay, sq_w + (size_t)i*65536, sq_b + i*HH, qb, 0);
        gemm_kernel<<<dim3(129,4), 256>>>(nodes, skT + (size_t)i*65536,
                                          sk_b + i*HH, kmat, YROWS, HH,
                                          EP_BIAS|AMODE_Y, relay, nullptr);
        star_att<<<BB, 256>>>(qb, kmat, mask, attb);
        vecmm<<<BB, 256>>>(attb, so_w + (size_t)i*65536, so_b + i*HH, relay, 1);
        mask_nodes<<<NROWS, 256>>>(mask, nodes);
    }

    cudaMemcpyAsync(d_out, nodes, (size_t)NROWS*HH*sizeof(float),
                    cudaMemcpyDeviceToDevice);
    cudaMemcpyAsync((float*)d_out + (size_t)NROWS*HH, relay,
                    (size_t)BB*HH*sizeof(float), cudaMemcpyDeviceToDevice);
}

// round 4
// speedup vs baseline: 1.1920x; 1.1920x over previous
#include <cuda_runtime.h>
#include <cuda_bf16.h>
#include <math.h>

// ---------------- problem constants ----------------
#define BB 16
#define LL 512
#define HH 256
#define NHH 8
#define HDD 32
#define ITER 2
#define PCOLS 272        // NH * 34  (slots: 0=a1, 1=a2, 2..33=Fw cols)
#define NROWS (BB*LL)    // 8192
#define YROWS (BB*(LL+1))// 8208
#define NEGV  (-9e15f)

// ---------------- scratch (device globals, no alloc) ----------------
__device__ float g_W1[HH*PCOLS];
__device__ float g_W2[HH*PCOLS];
__device__ float g_W3[HH*PCOLS];
__device__ float g_cb[PCOLS];
__device__ float g_D [NROWS*PCOLS];
__device__ float g_P [NROWS*PCOLS];
__device__ float g_R [BB*PCOLS];
__device__ float g_nodes[NROWS*HH];
__device__ float g_xn   [NROWS*HH];
__device__ float g_temp [NROWS*HH];
__device__ float g_kmat [YROWS*HH];
__device__ float g_relay[BB*HH];
__device__ float g_q    [BB*HH];
__device__ float g_attv [BB*HH];
__device__ float g_skT  [2*HH*HH];

// ---------------- weight folding ----------------
__global__ __launch_bounds__(256) void build_w1(const float* __restrict__ Wq,
        const float* __restrict__ a1, const float* __restrict__ a2,
        const float* __restrict__ fw, float* __restrict__ W1)
{
    int c = blockIdx.x;                 // 0..271
    int n = c / 34, s = c % 34;
    int t = threadIdx.x;                // 0..255
    __shared__ float cvec[256];
    float cv;
    if (s == 0)      cv = a1[n*768 + t];
    else if (s == 1) cv = a2[n*768 + t];
    else             cv = fw[(size_t)n*24576 + t*32 + (s-2)];
    cvec[t] = cv;
    __syncthreads();
    const float* wqn = Wq + (size_t)n*65536;
    float sum = 0.f;
    #pragma unroll 8
    for (int d = 0; d < 256; d++) sum += wqn[d*256 + t] * cvec[d];
    W1[t*PCOLS + c] = sum;
}

__global__ __launch_bounds__(256) void build_misc(const float* __restrict__ a1,
        const float* __restrict__ a2, const float* __restrict__ fw,
        const float* __restrict__ bq, const float* __restrict__ skw,
        float* __restrict__ W2, float* __restrict__ W3,
        float* __restrict__ cb, float* __restrict__ skT)
{
    int idx = blockIdx.x*256 + threadIdx.x;
    if (idx < HH*PCOLS) {
        int k = idx / PCOLS, c = idx % PCOLS;
        int n = c / 34, s = c % 34;
        int re = 256 + 2*k, ro = re + 1;
        float ve, vo;
        if (s == 0)      { ve = a1[n*768+re]; vo = a1[n*768+ro]; }
        else if (s == 1) { ve = a2[n*768+re]; vo = a2[n*768+ro]; }
        else { ve = fw[(size_t)n*24576 + re*32 + (s-2)];
               vo = fw[(size_t)n*24576 + ro*32 + (s-2)]; }
        W2[idx] = ve; W3[idx] = vo;
    }
    int idx2 = idx - HH*PCOLS;
    if (idx2 >= 0 && idx2 < 2*65536) {
        int i = idx2 >> 16, rem = idx2 & 65535;
        int k = rem >> 8, c = rem & 255;
        skT[(size_t)i*65536 + k*256 + c] = skw[(size_t)i*65536 + c*256 + k];
    }
    if (idx < PCOLS) {
        int n = idx / 34, s = idx % 34;
        float sum = 0.f;
        for (int d = 0; d < 256; d++) {
            float cv = (s==0) ? a1[n*768+d] : (s==1) ? a2[n*768+d]
                     : fw[(size_t)n*24576 + d*32 + (s-2)];
            sum += bq[n*256+d] * cv;
        }
        cb[idx] = sum;
    }
}

__global__ __launch_bounds__(256) void relay_init(const float* __restrict__ data,
                                                  float* __restrict__ relay)
{
    int b = blockIdx.x, h = threadIdx.x;
    float s = 0.f;
    for (int l = 0; l < LL; l++) s += data[((size_t)b*LL + l)*HH + h];
    relay[b*HH + h] = s * (1.f/512.f);
}

// ---------------- GEMM: C[M,N] = A[M,256] @ B[256,N] (+ epilogue) ----------
// 128x64 block tile, 256 threads, 8x4 per thread.
#define EP_BIAS 1
#define EP_FC   2   // leaky-relu + residual + pad-mask
#define AMODE_Y 4   // A rows come from [relay_b ; nodes_b]
#define EP_PD   8   // += D + R(broadcast per batch)
__global__ __launch_bounds__(256) void gemm_kernel(const float* __restrict__ A,
        const float* __restrict__ Bm, const float* __restrict__ bias,
        float* __restrict__ C, int M, int N, int mode,
        const float* __restrict__ relayv, const float* __restrict__ resid,
        const float* __restrict__ Dm, const float* __restrict__ Rm,
        const int* __restrict__ maskp)
{
    __shared__ __align__(16) float As[16][128];
    __shared__ __align__(16) float Bs[16][64];
    int tid = threadIdx.x;
    int row0 = blockIdx.x * 128;
    int col0 = blockIdx.y * 64;
    int tx = tid & 15;          // col group (x4)
    int ty = tid >> 4;          // row group (x8)
    int aRow = tid & 127;       // A-load row
    int kqBase = (tid >> 7) * 2;// 0 or 2
    int bRow = tid >> 4;        // 0..15
    int bCol = (tid & 15) * 4;  // 0..60

    float acc[8][4];
    #pragma unroll
    for (int i = 0; i < 8; i++)
        #pragma unroll
        for (int j = 0; j < 4; j++) acc[i][j] = 0.f;

    for (int k0 = 0; k0 < 256; k0 += 16) {
        // load A tile (transposed into As[k][row])
        int gr = row0 + aRow;
        const float* arow = nullptr;
        if (gr < M) {
            if (mode & AMODE_Y) {
                int b = gr / 513, lr = gr - b*513;
                arow = (lr == 0) ? (relayv + b*HH)
                                 : (A + (size_t)(b*LL + lr - 1)*HH);
            } else arow = A + (size_t)gr*256;
        }
        #pragma unroll
        for (int u = 0; u < 2; u++) {
            int kq = kqBase + u;            // 0..3
            float4 av = make_float4(0.f,0.f,0.f,0.f);
            if (arow) av = *(const float4*)(arow + k0 + kq*4);
            As[kq*4+0][aRow] = av.x; As[kq*4+1][aRow] = av.y;
            As[kq*4+2][aRow] = av.z; As[kq*4+3][aRow] = av.w;
        }
        // load B tile
        {
            int gk = k0 + bRow;
            int gc = col0 + bCol;
            float4 bv = make_float4(0.f,0.f,0.f,0.f);
            if (gc + 4 <= N) bv = *(const float4*)(Bm + (size_t)gk*N + gc);
            *(float4*)&Bs[bRow][bCol] = bv;
        }
        __syncthreads();
        #pragma unroll
        for (int kk = 0; kk < 16; kk++) {
            float4 a0 = *(const float4*)&As[kk][ty*8];
            float4 a1 = *(const float4*)&As[kk][ty*8+4];
            float4 b0 = *(const float4*)&Bs[kk][tx*4];
            float ar[8] = {a0.x,a0.y,a0.z,a0.w,a1.x,a1.y,a1.z,a1.w};
            float br[4] = {b0.x,b0.y,b0.z,b0.w};
            #pragma unroll
            for (int i = 0; i < 8; i++)
                #pragma unroll
                for (int j = 0; j < 4; j++) acc[i][j] += ar[i]*br[j];
        }
        __syncthreads();
    }
    #pragma unroll
    for (int i = 0; i < 8; i++) {
        int r = row0 + ty*8 + i;
        if (r >= M) continue;
        int b = r >> 9, l = r & 511;
        #pragma unroll
        for (int j = 0; j < 4; j++) {
            int c = col0 + tx*4 + j;
            if (c >= N) continue;
            float v = acc[i][j];
            if (mode & EP_BIAS) v += bias[c];
            if (mode & EP_PD)
                v += Dm[(size_t)r*N + c] + Rm[b*PCOLS + c];
            if (mode & EP_FC) {
                v = v > 0.f ? v : 0.01f*v;
                v += resid[(size_t)r*N + c];
                if (maskp[b*LL + l] == 0) v = 0.f;
            }
            C[(size_t)r*N + c] = v;
        }
    }
}

// ---------------- LayerNorm ----------------
__global__ __launch_bounds__(256) void ln_kernel(const float* __restrict__ nodes,
        const float* __restrict__ gam, const float* __restrict__ bet,
        float* __restrict__ xn)
{
    int r = blockIdx.x, t = threadIdx.x;
    float x = nodes[(size_t)r*HH + t];
    float s = x, s2 = x*x;
    #pragma unroll
    for (int off = 16; off; off >>= 1) {
        s  += __shfl_xor_sync(0xffffffffu, s,  off);
        s2 += __shfl_xor_sync(0xffffffffu, s2, off);
    }
    __shared__ float sh1[8], sh2[8];
    int w = t >> 5, lane = t & 31;
    if (lane == 0) { sh1[w] = s; sh2[w] = s2; }
    __syncthreads();
    s = 0.f; s2 = 0.f;
    #pragma unroll
    for (int i = 0; i < 8; i++) { s += sh1[i]; s2 += sh2[i]; }
    float m = s * (1.f/256.f);
    float v = s2 * (1.f/256.f) - m*m;
    xn[(size_t)r*HH + t] = (x - m) * rsqrtf(v + 1e-5f) * gam[t] + bet[t];
}

// ---------------- relay projection: R = relay @ W3 ----------------
__global__ void relayproj(const float* __restrict__ relay,
        const float* __restrict__ W3, float* __restrict__ R)
{
    int b = blockIdx.x, c = threadIdx.x; // 272 threads
    __shared__ float vsh[256];
    if (c < 256) vsh[c] = relay[b*HH + c];
    __syncthreads();
    float s = 0.f;
    #pragma unroll 8
    for (int k = 0; k < 256; k++) s += vsh[k] * W3[k*PCOLS + c];
    R[b*PCOLS + c] = s;
}

// ---------------- GAT attention (fused softmax + AV) ----------------
// One block per (head n, batch b). P already contains +D +R +cb.
// 512 threads (16 warps), warp-per-row; g tile padded to stride 36 for LDS.128.
#define GST 36
__global__ __launch_bounds__(512) void gat_att(const float* __restrict__ P,
        const float* __restrict__ Fb, const int* __restrict__ edge,
        float* __restrict__ temp)
{
    extern __shared__ float sm[];
    float* gsh  = sm;                 // [512][GST]
    float* eish = sm + 512*GST;       // [512]
    float* ejsh = eish + 512;         // [512]
    int blk = blockIdx.x;
    int n = blk >> 4, b = blk & 15;
    int tid = threadIdx.x;
    int base = n * 34;
    int lane = tid & 31;
    int warp = tid >> 5;              // 0..15

    for (int j = warp; j < 512; j += 16) {
        gsh[j*GST + lane] = P[(size_t)(b*LL + j)*PCOLS + base + 2 + lane];
    }
    for (int j = tid; j < 512; j += 512) {
        size_t idx = (size_t)(b*LL + j)*PCOLS + base;
        eish[j] = P[idx];
        ejsh[j] = P[idx+1];
    }
    __syncthreads();

    float Fbv = Fb[n*32 + lane];
    const int* erow_base = edge + (size_t)b*LL*LL;

    for (int i = warp; i < 512; i += 16) {
        float ei = eish[i];
        const int* erow = erow_base + (size_t)i*LL;
        int ev[16];
        #pragma unroll
        for (int t = 0; t < 16; t++) ev[t] = erow[t*32 + lane];

        float e16[16];
        float m = -INFINITY;
        #pragma unroll
        for (int t = 0; t < 16; t++) {
            float e = ei + ejsh[t*32 + lane];
            e = e >= 0.f ? e : 0.2f*e;
            if (ev[t] <= 0) e = NEGV;
            e16[t] = e;
            m = fmaxf(m, e);
        }
        #pragma unroll
        for (int off = 16; off; off >>= 1)
            m = fmaxf(m, __shfl_xor_sync(0xffffffffu, m, off));

        float s = 0.f;
        float acc[32];
        #pragma unroll
        for (int d2 = 0; d2 < 32; d2++) acc[d2] = 0.f;
        #pragma unroll
        for (int t = 0; t < 16; t++) {
            float w = __expf(e16[t] - m);
            s += w;
            const float* gj = &gsh[(t*32 + lane)*GST];
            #pragma unroll
            for (int d2 = 0; d2 < 32; d2++) acc[d2] += w * gj[d2];
        }
        // denominator: reduce-to-all (scalar)
        #pragma unroll
        for (int off = 16; off; off >>= 1)
            s += __shfl_xor_sync(0xffffffffu, s, off);
        // accumulators: reduce-scatter so lane d ends with dim d in acc[0]
        #pragma unroll
        for (int off = 16; off; off >>= 1) {
            #pragma unroll
            for (int k = 0; k < off; k++) {
                float keep = (lane & off) ? acc[k+off] : acc[k];
                float send = (lane & off) ? acc[k]     : acc[k+off];
                float other = __shfl_xor_sync(0xffffffffu, send, off);
                acc[k] = keep + other;
            }
        }
        float outv = acc[0] / s + Fbv;
        outv = outv > 0.f ? outv : expm1f(outv);   // elu
        temp[(size_t)(b*LL + i)*HH + n*32 + lane] = outv;
    }
}

// ---------------- small vec @ W.T (+bias, optional leaky) ----------------
__global__ __launch_bounds__(256) void vecmm(const float* __restrict__ vin,
        const float* __restrict__ W, const float* __restrict__ bias,
        float* __restrict__ vout, int lrelu)
{
    int b = blockIdx.x, c = threadIdx.x;
    __shared__ float vsh[256];
    vsh[c] = vin[b*HH + c];
    __syncthreads();
    const float* wr = W + (size_t)c*256;
    float s = bias[c];
    #pragma unroll 8
    for (int k = 0; k < 256; k++) s += wr[k] * vsh[k];
    if (lrelu) s = s > 0.f ? s : 0.01f*s;
    vout[b*HH + c] = s;
}

// ---------------- star attention ----------------
__global__ __launch_bounds__(256) void star_att(const float* __restrict__ q,
        const float* __restrict__ kmat, const int* __restrict__ mask,
        float* __restrict__ att)
{
    int b = blockIdx.x;
    int warp = threadIdx.x >> 5, lane = threadIdx.x & 31;
    __shared__ float qsh[8][32];
    qsh[warp][lane] = q[b*HH + warp*32 + lane];
    __syncwarp();
    const float scale = 0.17677669529663687f;   // 1/sqrt(32)
    float pre[17];
    float m = -INFINITY;
    #pragma unroll
    for (int t = 0; t < 17; t++) {
        int l = t*32 + lane;
        float p = -INFINITY;
        if (l < 513) {
            bool masked = (l > 0) && (mask[b*LL + l - 1] == 0);
            if (!masked) {
                const float* kr = kmat + ((size_t)b*513 + l)*HH + warp*32;
                float sacc = 0.f;
                #pragma unroll
                for (int d2 = 0; d2 < 32; d2++) sacc += qsh[warp][d2]*kr[d2];
                p = sacc * scale;
            }
        }
        pre[t] = p;
        m = fmaxf(m, p);
    }
    #pragma unroll
    for (int off = 16; off; off >>= 1)
        m = fmaxf(m, __shfl_xor_sync(0xffffffffu, m, off));
    float s = 0.f;
    float acc[32];
    #pragma unroll
    for (int d2 = 0; d2 < 32; d2++) acc[d2] = 0.f;
    #pragma unroll
    for (int t = 0; t < 17; t++) {
        int l = t*32 + lane;
        if (l < 513) {
            float w = __expf(pre[t] - m);   // 0 for masked
            s += w;
            const float* kr = kmat + ((size_t)b*513 + l)*HH + warp*32;
            #pragma unroll
            for (int d2 = 0; d2 < 32; d2++) acc[d2] += w * kr[d2];
        }
    }
    #pragma unroll
    for (int off = 16; off; off >>= 1)
        s += __shfl_xor_sync(0xffffffffu, s, off);
    #pragma unroll
    for (int off = 16; off; off >>= 1) {
        #pragma unroll
        for (int k = 0; k < off; k++) {
            float keep = (lane & off) ? acc[k+off] : acc[k];
            float send = (lane & off) ? acc[k]     : acc[k+off];
            float other = __shfl_xor_sync(0xffffffffu, send, off);
            acc[k] = keep + other;
        }
    }
    att[b*HH + warp*32 + lane] = acc[0] / s;
}

// ---------------- launch ----------------
extern "C" void kernel_launch(void* const* d_in, const int* in_sizes, int n_in,
                              void* d_out, int out_size)
{
    const float* data   = (const float*)d_in[0];
    const float* WQw    = (const float*)d_in[1];
    const float* WQb    = (const float*)d_in[2];
    const float* a1     = (const float*)d_in[3];
    const float* a2     = (const float*)d_in[4];
    const float* fcw_g  = (const float*)d_in[5];   // gat_fc_w
    const float* fcb_g  = (const float*)d_in[6];   // gat_fc_b
    const float* norm_g = (const float*)d_in[7];
    const float* norm_b = (const float*)d_in[8];
    const float* sq_w   = (const float*)d_in[9];
    const float* sq_b   = (const float*)d_in[10];
    const float* sk_w   = (const float*)d_in[11];
    const float* sk_b   = (const float*)d_in[12];
    const float* so_w   = (const float*)d_in[13];
    const float* so_b   = (const float*)d_in[14];
    const float* fc_w   = (const float*)d_in[15];
    const float* fc_b   = (const float*)d_in[16];
    const int*   mask   = (const int*)d_in[17];
    const int*   edge   = (const int*)d_in[18];

    float *W1,*W2,*W3,*cb,*D,*P,*R,*nodes,*xn,*temp,*kmat,*relay,*qb,*attb,*skT;
    cudaGetSymbolAddress((void**)&W1, g_W1);
    cudaGetSymbolAddress((void**)&W2, g_W2);
    cudaGetSymbolAddress((void**)&W3, g_W3);
    cudaGetSymbolAddress((void**)&cb, g_cb);
    cudaGetSymbolAddress((void**)&D,  g_D);
    cudaGetSymbolAddress((void**)&P,  g_P);
    cudaGetSymbolAddress((void**)&R,  g_R);
    cudaGetSymbolAddress((void**)&nodes, g_nodes);
    cudaGetSymbolAddress((void**)&xn,    g_xn);
    cudaGetSymbolAddress((void**)&temp,  g_temp);
    cudaGetSymbolAddress((void**)&kmat,  g_kmat);
    cudaGetSymbolAddress((void**)&relay, g_relay);
    cudaGetSymbolAddress((void**)&qb,    g_q);
    cudaGetSymbolAddress((void**)&attb,  g_attv);
    cudaGetSymbolAddress((void**)&skT,   g_skT);

    const int gat_smem = (512*GST + 1024) * sizeof(float);  // 77824 B
    cudaFuncSetAttribute(gat_att, cudaFuncAttributeMaxDynamicSharedMemorySize,
                         gat_smem);

    build_w1<<<PCOLS, 256>>>(WQw, a1, a2, fcw_g, W1);
    build_misc<<<784, 256>>>(a1, a2, fcw_g, WQb, sk_w, W2, W3, cb, skT);
    relay_init<<<BB, 256>>>(data, relay);
    cudaMemcpyAsync(nodes, data, (size_t)NROWS*HH*sizeof(float),
                    cudaMemcpyDeviceToDevice);
    // D = data @ W2
    gemm_kernel<<<dim3(64,5), 256>>>(data, W2, nullptr, D, NROWS, PCOLS, 0,
                                     nullptr, nullptr, nullptr, nullptr, nullptr);

    for (int i = 0; i < ITER; i++) {
        ln_kernel<<<NROWS, 256>>>(nodes, norm_g + i*HH, norm_b + i*HH, xn);
        relayproj<<<BB, PCOLS>>>(relay, W3, R);
        // P = xn @ W1 + cb + D + R   (everything gat_att needs)
        gemm_kernel<<<dim3(64,5), 256>>>(xn, W1, cb, P, NROWS, PCOLS,
                                         EP_BIAS|EP_PD, nullptr, nullptr,
                                         D, R, nullptr);
        gat_att<<<128, 512, gat_smem>>>(P, fcb_g, edge, temp);
        // nodes = mask( nodes + leaky(temp @ fc_w + fc_b) )
        gemm_kernel<<<dim3(64,4), 256>>>(temp, fc_w, fc_b, nodes, NROWS, HH,
                                         EP_BIAS|EP_FC, nullptr, nodes,
                                         nullptr, nullptr, mask);
        vecmm<<<BB, 256>>>(relay, sq_w + (size_t)i*65536, sq_b + i*HH, qb, 0);
        gemm_kernel<<<dim3(65,4), 256>>>(nodes, skT + (size_t)i*65536,
                                         sk_b + i*HH, kmat, YROWS, HH,
                                         EP_BIAS|AMODE_Y, relay, nullptr,
                                         nullptr, nullptr, nullptr);
        star_att<<<BB, 256>>>(qb, kmat, mask, attb);
        vecmm<<<BB, 256>>>(attb, so_w + (size_t)i*65536, so_b + i*HH, relay, 1);
    }

    cudaMemcpyAsync(d_out, nodes, (size_t)NROWS*HH*sizeof(float),
                    cudaMemcpyDeviceToDevice);
    cudaMemcpyAsync((float*)d_out + (size_t)NROWS*HH, relay,
                    (size_t)BB*HH*sizeof(float), cudaMemcpyDeviceToDevice);
}